// round 7
// baseline (speedup 1.0000x reference)
#include <cuda_runtime.h>
#include <cuda_fp16.h>
#include <stdint.h>

#define T_SEQ   4096
#define C_DIM   768
#define H_NUM   12
#define D_HEAD  64
#define QKV_N   2304

// ------------------------- scratch (allocation-free) -------------------------
__device__ __half g_xh  [T_SEQ * C_DIM];
__device__ __half g_wah [C_DIM * QKV_N];
__device__ __half g_wph [C_DIM * C_DIM];
__device__ __half g_qkvh[T_SEQ * QKV_N];
__device__ __half g_vt  [C_DIM * T_SEQ];   // V transposed: [channel(h*64+d)][t]
__device__ __half g_yh  [T_SEQ * C_DIM];

// ------------------------------ helpers --------------------------------------
__device__ __forceinline__ void mma16816(float* c,
    uint32_t a0, uint32_t a1, uint32_t a2, uint32_t a3,
    uint32_t b0, uint32_t b1)
{
    asm volatile(
        "mma.sync.aligned.m16n8k16.row.col.f32.f16.f16.f32 "
        "{%0,%1,%2,%3},{%4,%5,%6,%7},{%8,%9},{%0,%1,%2,%3};"
        : "+f"(c[0]), "+f"(c[1]), "+f"(c[2]), "+f"(c[3])
        : "r"(a0), "r"(a1), "r"(a2), "r"(a3), "r"(b0), "r"(b1));
}

__device__ __forceinline__ uint32_t packf2h(float lo, float hi) {
    uint32_t r;
    asm("cvt.rn.f16x2.f32 %0, %1, %2;" : "=r"(r) : "f"(hi), "f"(lo));
    return r;
}

__device__ __forceinline__ uint32_t smem_u32(const void* p) {
    return (uint32_t)__cvta_generic_to_shared(p);
}
__device__ __forceinline__ void cp16(uint32_t dst, const void* src) {
    asm volatile("cp.async.cg.shared.global [%0], [%1], 16;" :: "r"(dst), "l"(src));
}
__device__ __forceinline__ void cp_commit() {
    asm volatile("cp.async.commit_group;");
}
__device__ __forceinline__ void cp_wait1() {
    asm volatile("cp.async.wait_group 1;");
}
__device__ __forceinline__ void cp_wait0() {
    asm volatile("cp.async.wait_group 0;");
}
__device__ __forceinline__ void ldsm4(uint32_t* r, uint32_t a) {
    asm volatile("ldmatrix.sync.aligned.m8n8.x4.shared.b16 {%0,%1,%2,%3}, [%4];"
                 : "=r"(r[0]), "=r"(r[1]), "=r"(r[2]), "=r"(r[3]) : "r"(a));
}
__device__ __forceinline__ void ldsm4t(uint32_t* r, uint32_t a) {
    asm volatile("ldmatrix.sync.aligned.m8n8.x4.trans.shared.b16 {%0,%1,%2,%3}, [%4];"
                 : "=r"(r[0]), "=r"(r[1]), "=r"(r[2]), "=r"(r[3]) : "r"(a));
}

// exp2 on the MUFU pipe (single EX2)
__device__ __forceinline__ float ex2(float x) {
    float r; asm("ex2.approx.f32 %0, %1;" : "=f"(r) : "f"(x)); return r;
}
// exp2 on the FMA/ALU pipes (degree-4 poly, rel err ~3e-5) — runs parallel to MUFU
__device__ __forceinline__ float fexp2(float x) {
    x = fmaxf(x, -80.0f);
    float r;
    asm("cvt.rni.f32.f32 %0, %1;" : "=f"(r) : "f"(x));
    float f = x - r;
    float p = fmaf(f, fmaf(f, fmaf(f, fmaf(f, 0.0096181291f, 0.0555041086f),
                                   0.2402265069f), 0.6931471806f), 1.0f);
    int e = (int)r;
    return __int_as_float(__float_as_int(p) + (e << 23));
}

// ------------------------- fp32 -> fp16 conversion ---------------------------
__global__ void cvt_f2h(const float4* __restrict__ src, uint2* __restrict__ dst, int n4)
{
    int i = blockIdx.x * blockDim.x + threadIdx.x;
    if (i >= n4) return;
    float4 v = src[i];
    uint2 o;
    o.x = packf2h(v.x, v.y);
    o.y = packf2h(v.z, v.w);
    dst[i] = o;
}

// ------------------- V transpose: [t][1536 + c] -> [c][t] ---------------------
__global__ __launch_bounds__(256) void transpose_v()
{
    __shared__ __half tile[32][36];
    const int tb = blockIdx.x * 32;
    const int cb = blockIdx.y * 32;
    const int r  = threadIdx.x >> 3;
    const int c4 = (threadIdx.x & 7) * 4;

    *(uint2*)&tile[r][c4] =
        *(const uint2*)&g_qkvh[(size_t)(tb + r) * QKV_N + 1536 + cb + c4];
    __syncthreads();

    __half2 h0 = __halves2half2(tile[c4 + 0][r], tile[c4 + 1][r]);
    __half2 h1 = __halves2half2(tile[c4 + 2][r], tile[c4 + 3][r]);
    uint2 o = { *(uint32_t*)&h0, *(uint32_t*)&h1 };
    *(uint2*)&g_vt[(size_t)(cb + r) * T_SEQ + tb + c4] = o;
}

// ----------------------- fp16 MMA GEMM with fused bias -----------------------
template<bool OUT_F32>
__global__ __launch_bounds__(256) void hgemm_bias(
    const __half* __restrict__ A, const __half* __restrict__ B,
    const float* __restrict__ bias, void* __restrict__ Cout,
    int M, int N, int K)
{
    __shared__ __half As[2][128][40];   // [m][k], pad 8
    __shared__ __half Bs[2][32][136];   // [k][n], pad 8

    const int tid = threadIdx.x;
    const int l   = tid & 31;
    const int wid = tid >> 5;
    const int wm  = (wid & 3) * 32;
    const int wn  = (wid >> 2) * 64;
    const int brow = blockIdx.y * 128;
    const int bcol = blockIdx.x * 128;

    const int ar = tid >> 1, ac = (tid & 1) * 16;
    const int bkr = tid >> 3, bc = (tid & 7) * 16;

    float acc[2][8][4];
#pragma unroll
    for (int mi = 0; mi < 2; mi++)
#pragma unroll
        for (int nt = 0; nt < 8; nt++)
#pragma unroll
            for (int j = 0; j < 4; j++) acc[mi][nt][j] = 0.0f;

    const int NK = K / 32;

    {
        const __half* asrc = A + (size_t)(brow + ar) * K + ac;
        const __half* bsrc = B + (size_t)bkr * N + bcol + bc;
        cp16(smem_u32(&As[0][ar][ac]),     asrc);
        cp16(smem_u32(&As[0][ar][ac + 8]), asrc + 8);
        cp16(smem_u32(&Bs[0][bkr][bc]),     bsrc);
        cp16(smem_u32(&Bs[0][bkr][bc + 8]), bsrc + 8);
        cp_commit();
    }

    for (int kt = 0; kt < NK; kt++) {
        const int buf = kt & 1;
        if (kt + 1 < NK) {
            const int k0 = (kt + 1) * 32;
            const __half* asrc = A + (size_t)(brow + ar) * K + k0 + ac;
            const __half* bsrc = B + (size_t)(k0 + bkr) * N + bcol + bc;
            cp16(smem_u32(&As[buf ^ 1][ar][ac]),     asrc);
            cp16(smem_u32(&As[buf ^ 1][ar][ac + 8]), asrc + 8);
            cp16(smem_u32(&Bs[buf ^ 1][bkr][bc]),     bsrc);
            cp16(smem_u32(&Bs[buf ^ 1][bkr][bc + 8]), bsrc + 8);
            cp_commit();
            cp_wait1();
        } else {
            cp_wait0();
        }
        __syncthreads();

#pragma unroll
        for (int ks = 0; ks < 2; ks++) {
            uint32_t ra[2][4];
#pragma unroll
            for (int mi = 0; mi < 2; mi++)
                ldsm4(ra[mi], smem_u32(&As[buf][wm + mi * 16 + (l & 15)][ks * 16 + (l >> 4) * 8]));
#pragma unroll
            for (int ntp = 0; ntp < 4; ntp++) {
                uint32_t rb[4];
                ldsm4t(rb, smem_u32(&Bs[buf][ks * 16 + (l & 15)][wn + ntp * 16 + (l >> 4) * 8]));
                mma16816(acc[0][2 * ntp],     ra[0][0], ra[0][1], ra[0][2], ra[0][3], rb[0], rb[1]);
                mma16816(acc[1][2 * ntp],     ra[1][0], ra[1][1], ra[1][2], ra[1][3], rb[0], rb[1]);
                mma16816(acc[0][2 * ntp + 1], ra[0][0], ra[0][1], ra[0][2], ra[0][3], rb[2], rb[3]);
                mma16816(acc[1][2 * ntp + 1], ra[1][0], ra[1][1], ra[1][2], ra[1][3], rb[2], rb[3]);
            }
        }
        __syncthreads();
    }

#pragma unroll
    for (int nt = 0; nt < 8; nt++) {
        int col = bcol + wn + nt * 8 + (l & 3) * 2;
        float2 bv = *(const float2*)&bias[col];
#pragma unroll
        for (int mi = 0; mi < 2; mi++) {
            int r0 = brow + wm + mi * 16 + (l >> 2);
            int r1 = r0 + 8;
            float v0 = acc[mi][nt][0] + bv.x;
            float v1 = acc[mi][nt][1] + bv.y;
            float v2 = acc[mi][nt][2] + bv.x;
            float v3 = acc[mi][nt][3] + bv.y;
            if (OUT_F32) {
                float* C = (float*)Cout;
                *(float2*)&C[(size_t)r0 * N + col] = make_float2(v0, v1);
                *(float2*)&C[(size_t)r1 * N + col] = make_float2(v2, v3);
            } else {
                __half* C = (__half*)Cout;
                *(uint32_t*)&C[(size_t)r0 * N + col] = packf2h(v0, v1);
                *(uint32_t*)&C[(size_t)r1 * N + col] = packf2h(v2, v3);
            }
        }
    }
}

// --------------------- flash attention (fp16 mma, FA2) -----------------------
// 128 queries per block (8 warps x m16), 64-key double-buffered tiles.
// Paired-chunk schedule: block bx handles chunk bx and chunk 31-bx (66 tiles each).
// Softmax in log2 domain (log2e folded into Q scale); hybrid MUFU/poly exp;
// rescale skipped via warp vote when row maxima are unchanged.
__global__ __launch_bounds__(256) void flash_mma()
{
    __shared__ __half Ks[2][64][72];   // [key][d]
    __shared__ __half Vs[2][64][72];   // [d][key]

    const int h    = blockIdx.y;
    const int pair = blockIdx.x;       // 0..15
    const int tid  = threadIdx.x;
    const int w    = tid >> 5;
    const int l    = tid & 31;

    const int lr = tid >> 2;           // 0..63  (tile loader row)
    const int lc = (tid & 3) * 16;     // 0/16/32/48 (halves)

#pragma unroll 1
    for (int half = 0; half < 2; half++) {
        const int chunk = half ? (31 - pair) : pair;
        const int qb = chunk * 128;
        const int r0 = qb + w * 16 + (l >> 2);
        const int r1 = r0 + 8;

        // Q fragments pre-scaled by log2(e)/sqrt(64)  (softmax in log2 domain)
        uint32_t qa[4][4];
        {
            const __half2 sc = __float2half2_rn(0.125f * 1.44269504f);
#pragma unroll
            for (int ks = 0; ks < 4; ks++) {
                size_t c0 = (size_t)h * 64 + ks * 16 + (l & 3) * 2;
                __half2 v0 = *(const __half2*)&g_qkvh[(size_t)r0 * QKV_N + c0];
                __half2 v1 = *(const __half2*)&g_qkvh[(size_t)r1 * QKV_N + c0];
                __half2 v2 = *(const __half2*)&g_qkvh[(size_t)r0 * QKV_N + c0 + 8];
                __half2 v3 = *(const __half2*)&g_qkvh[(size_t)r1 * QKV_N + c0 + 8];
                v0 = __hmul2(v0, sc); v1 = __hmul2(v1, sc);
                v2 = __hmul2(v2, sc); v3 = __hmul2(v3, sc);
                qa[ks][0] = *(uint32_t*)&v0; qa[ks][1] = *(uint32_t*)&v1;
                qa[ks][2] = *(uint32_t*)&v2; qa[ks][3] = *(uint32_t*)&v3;
            }
        }

        float o[8][4];
#pragma unroll
        for (int dt = 0; dt < 8; dt++)
#pragma unroll
            for (int j = 0; j < 4; j++) o[dt][j] = 0.0f;
        float m0 = -1e30f, m1 = -1e30f, l0 = 0.0f, l1 = 0.0f;

        // prologue: stage tile 0
        {
            const __half* ksrc = &g_qkvh[(size_t)lr * QKV_N + 768 + h * 64 + lc];
            const __half* vsrc = &g_vt[(size_t)(h * 64 + lr) * T_SEQ + lc];
            cp16(smem_u32(&Ks[0][lr][lc]),     ksrc);
            cp16(smem_u32(&Ks[0][lr][lc + 8]), ksrc + 8);
            cp16(smem_u32(&Vs[0][lr][lc]),     vsrc);
            cp16(smem_u32(&Vs[0][lr][lc + 8]), vsrc + 8);
            cp_commit();
        }

        const int ntiles = qb / 64 + 2;   // keys 0 .. qb+127
        for (int it = 0; it < ntiles; it++) {
            const int kt  = it * 64;
            const int buf = it & 1;
            if (it + 1 < ntiles) {
                const int kn = kt + 64;
                const __half* ksrc = &g_qkvh[(size_t)(kn + lr) * QKV_N + 768 + h * 64 + lc];
                const __half* vsrc = &g_vt[(size_t)(h * 64 + lr) * T_SEQ + kn + lc];
                cp16(smem_u32(&Ks[buf ^ 1][lr][lc]),     ksrc);
                cp16(smem_u32(&Ks[buf ^ 1][lr][lc + 8]), ksrc + 8);
                cp16(smem_u32(&Vs[buf ^ 1][lr][lc]),     vsrc);
                cp16(smem_u32(&Vs[buf ^ 1][lr][lc + 8]), vsrc + 8);
                cp_commit();
                cp_wait1();
            } else {
                cp_wait0();
            }
            __syncthreads();

            // S = Q K^T  (log2-scaled logits)
            float s[8][4];
#pragma unroll
            for (int nt = 0; nt < 8; nt++)
#pragma unroll
                for (int j = 0; j < 4; j++) s[nt][j] = 0.0f;
#pragma unroll
            for (int ks = 0; ks < 4; ks++) {
#pragma unroll
                for (int ntp = 0; ntp < 4; ntp++) {
                    uint32_t rb[4];
                    ldsm4(rb, smem_u32(&Ks[buf][ntp * 16 + (l & 7) + ((l & 16) >> 1)][ks * 16 + (l & 8)]));
                    mma16816(s[2 * ntp],     qa[ks][0], qa[ks][1], qa[ks][2], qa[ks][3], rb[0], rb[1]);
                    mma16816(s[2 * ntp + 1], qa[ks][0], qa[ks][1], qa[ks][2], qa[ks][3], rb[2], rb[3]);
                }
            }

            // causal mask (last two tiles of each chunk only)
            if (kt + 64 > qb) {
#pragma unroll
                for (int nt = 0; nt < 8; nt++) {
                    int col = kt + nt * 8 + (l & 3) * 2;
                    if (col     > r0) s[nt][0] = -1e30f;
                    if (col + 1 > r0) s[nt][1] = -1e30f;
                    if (col     > r1) s[nt][2] = -1e30f;
                    if (col + 1 > r1) s[nt][3] = -1e30f;
                }
            }

            // online softmax (base 2)
            float mt0 = -1e30f, mt1 = -1e30f;
#pragma unroll
            for (int nt = 0; nt < 8; nt++) {
                mt0 = fmaxf(mt0, fmaxf(s[nt][0], s[nt][1]));
                mt1 = fmaxf(mt1, fmaxf(s[nt][2], s[nt][3]));
            }
            mt0 = fmaxf(mt0, __shfl_xor_sync(0xFFFFFFFF, mt0, 1));
            mt0 = fmaxf(mt0, __shfl_xor_sync(0xFFFFFFFF, mt0, 2));
            mt1 = fmaxf(mt1, __shfl_xor_sync(0xFFFFFFFF, mt1, 1));
            mt1 = fmaxf(mt1, __shfl_xor_sync(0xFFFFFFFF, mt1, 2));

            // rescale only when some row max grew (warp vote)
            if (__any_sync(0xFFFFFFFF, (mt0 > m0) | (mt1 > m1))) {
                float m0n = fmaxf(m0, mt0), m1n = fmaxf(m1, mt1);
                float corr0 = ex2(m0 - m0n), corr1 = ex2(m1 - m1n);
                m0 = m0n; m1 = m1n;
                l0 *= corr0; l1 *= corr1;
#pragma unroll
                for (int dt = 0; dt < 8; dt++) {
                    o[dt][0] *= corr0; o[dt][1] *= corr0;
                    o[dt][2] *= corr1; o[dt][3] *= corr1;
                }
            }

            // P = 2^(S - m): half MUFU, half polynomial (parallel pipes)
            uint32_t pa[4][4];
#pragma unroll
            for (int nt = 0; nt < 8; nt++) {
                float p0 = ex2  (s[nt][0] - m0);
                float p1 = fexp2(s[nt][1] - m0);
                float p2 = ex2  (s[nt][2] - m1);
                float p3 = fexp2(s[nt][3] - m1);
                l0 += p0 + p1;
                l1 += p2 + p3;
                int ks = nt >> 1, hi = (nt & 1) * 2;
                pa[ks][hi + 0] = packf2h(p0, p1);
                pa[ks][hi + 1] = packf2h(p2, p3);
            }

            // O += P V
#pragma unroll
            for (int ks = 0; ks < 4; ks++) {
#pragma unroll
                for (int dtp = 0; dtp < 4; dtp++) {
                    uint32_t rb[4];
                    ldsm4(rb, smem_u32(&Vs[buf][dtp * 16 + (l & 7) + ((l & 16) >> 1)][ks * 16 + (l & 8)]));
                    mma16816(o[2 * dtp],     pa[ks][0], pa[ks][1], pa[ks][2], pa[ks][3], rb[0], rb[1]);
                    mma16816(o[2 * dtp + 1], pa[ks][0], pa[ks][1], pa[ks][2], pa[ks][3], rb[2], rb[3]);
                }
            }
            __syncthreads();
        }

        // finalize
        l0 += __shfl_xor_sync(0xFFFFFFFF, l0, 1);
        l0 += __shfl_xor_sync(0xFFFFFFFF, l0, 2);
        l1 += __shfl_xor_sync(0xFFFFFFFF, l1, 1);
        l1 += __shfl_xor_sync(0xFFFFFFFF, l1, 2);
        float inv0 = 1.0f / l0, inv1 = 1.0f / l1;

#pragma unroll
        for (int dt = 0; dt < 8; dt++) {
            int d = h * 64 + dt * 8 + (l & 3) * 2;
            *(uint32_t*)&g_yh[(size_t)r0 * C_DIM + d] = packf2h(o[dt][0] * inv0, o[dt][1] * inv0);
            *(uint32_t*)&g_yh[(size_t)r1 * C_DIM + d] = packf2h(o[dt][2] * inv1, o[dt][3] * inv1);
        }
    }
}

// ------------------------------------------------------------------------------
extern "C" void kernel_launch(void* const* d_in, const int* in_sizes, int n_in,
                              void* d_out, int out_size)
{
    const float* x      = (const float*)d_in[0];
    const float* w_attn = (const float*)d_in[1];
    const float* b_attn = (const float*)d_in[2];
    const float* w_proj = (const float*)d_in[3];
    const float* b_proj = (const float*)d_in[4];
    float* out = (float*)d_out;

    __half *xh, *wah, *wph, *qkvh, *yh;
    cudaGetSymbolAddress((void**)&xh,   g_xh);
    cudaGetSymbolAddress((void**)&wah,  g_wah);
    cudaGetSymbolAddress((void**)&wph,  g_wph);
    cudaGetSymbolAddress((void**)&qkvh, g_qkvh);
    cudaGetSymbolAddress((void**)&yh,   g_yh);

    {
        int n4 = T_SEQ * C_DIM / 4;
        cvt_f2h<<<(n4 + 255) / 256, 256>>>((const float4*)x, (uint2*)xh, n4);
        n4 = C_DIM * QKV_N / 4;
        cvt_f2h<<<(n4 + 255) / 256, 256>>>((const float4*)w_attn, (uint2*)wah, n4);
        n4 = C_DIM * C_DIM / 4;
        cvt_f2h<<<(n4 + 255) / 256, 256>>>((const float4*)w_proj, (uint2*)wph, n4);
    }

    hgemm_bias<false><<<dim3(QKV_N / 128, T_SEQ / 128), 256>>>(
        xh, wah, b_attn, qkvh, T_SEQ, QKV_N, C_DIM);

    transpose_v<<<dim3(T_SEQ / 32, C_DIM / 32), 256>>>();

    flash_mma<<<dim3(16, H_NUM), 256>>>();

    hgemm_bias<true><<<dim3(C_DIM / 128, T_SEQ / 128), 256>>>(
        yh, wph, b_proj, out, T_SEQ, C_DIM, C_DIM);
}

// round 8
// speedup vs baseline: 1.0748x; 1.0748x over previous
#include <cuda_runtime.h>
#include <cuda_fp16.h>
#include <stdint.h>

#define T_SEQ   4096
#define C_DIM   768
#define H_NUM   12
#define D_HEAD  64
#define QKV_N   2304

// ------------------------- scratch (allocation-free) -------------------------
__device__ __half g_xh  [T_SEQ * C_DIM];
__device__ __half g_wah [C_DIM * QKV_N];
__device__ __half g_wph [C_DIM * C_DIM];
__device__ __half g_qkvh[T_SEQ * QKV_N];
__device__ __half g_vt  [C_DIM * T_SEQ];   // V transposed: [channel(h*64+d)][t]
__device__ __half g_yh  [T_SEQ * C_DIM];

// ------------------------------ helpers --------------------------------------
__device__ __forceinline__ void mma16816(float* c,
    uint32_t a0, uint32_t a1, uint32_t a2, uint32_t a3,
    uint32_t b0, uint32_t b1)
{
    asm volatile(
        "mma.sync.aligned.m16n8k16.row.col.f32.f16.f16.f32 "
        "{%0,%1,%2,%3},{%4,%5,%6,%7},{%8,%9},{%0,%1,%2,%3};"
        : "+f"(c[0]), "+f"(c[1]), "+f"(c[2]), "+f"(c[3])
        : "r"(a0), "r"(a1), "r"(a2), "r"(a3), "r"(b0), "r"(b1));
}

__device__ __forceinline__ uint32_t packf2h(float lo, float hi) {
    uint32_t r;
    asm("cvt.rn.f16x2.f32 %0, %1, %2;" : "=r"(r) : "f"(hi), "f"(lo));
    return r;
}

__device__ __forceinline__ uint32_t smem_u32(const void* p) {
    return (uint32_t)__cvta_generic_to_shared(p);
}
__device__ __forceinline__ void cp16(uint32_t dst, const void* src) {
    asm volatile("cp.async.cg.shared.global [%0], [%1], 16;" :: "r"(dst), "l"(src));
}
__device__ __forceinline__ void cp_commit() {
    asm volatile("cp.async.commit_group;");
}
__device__ __forceinline__ void cp_wait0() {
    asm volatile("cp.async.wait_group 0;");
}
__device__ __forceinline__ void ldsm4(uint32_t* r, uint32_t a) {
    asm volatile("ldmatrix.sync.aligned.m8n8.x4.shared.b16 {%0,%1,%2,%3}, [%4];"
                 : "=r"(r[0]), "=r"(r[1]), "=r"(r[2]), "=r"(r[3]) : "r"(a));
}
__device__ __forceinline__ void ldsm4t(uint32_t* r, uint32_t a) {
    asm volatile("ldmatrix.sync.aligned.m8n8.x4.trans.shared.b16 {%0,%1,%2,%3}, [%4];"
                 : "=r"(r[0]), "=r"(r[1]), "=r"(r[2]), "=r"(r[3]) : "r"(a));
}

// exp2 on the MUFU pipe
__device__ __forceinline__ float ex2(float x) {
    float r; asm("ex2.approx.f32 %0, %1;" : "=f"(r) : "f"(x)); return r;
}

// ------------------------- fp32 -> fp16 conversion ---------------------------
__global__ void cvt_f2h(const float4* __restrict__ src, uint2* __restrict__ dst, int n4)
{
    int i = blockIdx.x * blockDim.x + threadIdx.x;
    if (i >= n4) return;
    float4 v = src[i];
    uint2 o;
    o.x = packf2h(v.x, v.y);
    o.y = packf2h(v.z, v.w);
    dst[i] = o;
}

// ------------------- V transpose: [t][1536 + c] -> [c][t] ---------------------
__global__ __launch_bounds__(256) void transpose_v()
{
    __shared__ __half tile[32][36];
    const int tb = blockIdx.x * 32;
    const int cb = blockIdx.y * 32;
    const int r  = threadIdx.x >> 3;
    const int c4 = (threadIdx.x & 7) * 4;

    *(uint2*)&tile[r][c4] =
        *(const uint2*)&g_qkvh[(size_t)(tb + r) * QKV_N + 1536 + cb + c4];
    __syncthreads();

    __half2 h0 = __halves2half2(tile[c4 + 0][r], tile[c4 + 1][r]);
    __half2 h1 = __halves2half2(tile[c4 + 2][r], tile[c4 + 3][r]);
    uint2 o = { *(uint32_t*)&h0, *(uint32_t*)&h1 };
    *(uint2*)&g_vt[(size_t)(cb + r) * T_SEQ + tb + c4] = o;
}

// ----------------------- fp16 MMA GEMM with fused bias -----------------------
// Block 128x128x32, 8 warps (4M x 2N), warp tile 32x64.
// Double-buffered cp.async with ONE __syncthreads per k-tile:
//   wait0 -> sync -> issue prefetch -> compute.
template<bool OUT_F32>
__global__ __launch_bounds__(256) void hgemm_bias(
    const __half* __restrict__ A, const __half* __restrict__ B,
    const float* __restrict__ bias, void* __restrict__ Cout,
    int M, int N, int K)
{
    __shared__ __half As[2][128][40];   // [m][k], pad 8
    __shared__ __half Bs[2][32][136];   // [k][n], pad 8

    const int tid = threadIdx.x;
    const int l   = tid & 31;
    const int wid = tid >> 5;
    const int wm  = (wid & 3) * 32;
    const int wn  = (wid >> 2) * 64;
    const int brow = blockIdx.y * 128;
    const int bcol = blockIdx.x * 128;

    const int ar = tid >> 1, ac = (tid & 1) * 16;
    const int bkr = tid >> 3, bc = (tid & 7) * 16;

    float acc[2][8][4];
#pragma unroll
    for (int mi = 0; mi < 2; mi++)
#pragma unroll
        for (int nt = 0; nt < 8; nt++)
#pragma unroll
            for (int j = 0; j < 4; j++) acc[mi][nt][j] = 0.0f;

    const int NK = K / 32;

    {
        const __half* asrc = A + (size_t)(brow + ar) * K + ac;
        const __half* bsrc = B + (size_t)bkr * N + bcol + bc;
        cp16(smem_u32(&As[0][ar][ac]),     asrc);
        cp16(smem_u32(&As[0][ar][ac + 8]), asrc + 8);
        cp16(smem_u32(&Bs[0][bkr][bc]),     bsrc);
        cp16(smem_u32(&Bs[0][bkr][bc + 8]), bsrc + 8);
        cp_commit();
    }

    for (int kt = 0; kt < NK; kt++) {
        const int buf = kt & 1;
        cp_wait0();
        __syncthreads();

        if (kt + 1 < NK) {
            const int k0 = (kt + 1) * 32;
            const __half* asrc = A + (size_t)(brow + ar) * K + k0 + ac;
            const __half* bsrc = B + (size_t)(k0 + bkr) * N + bcol + bc;
            cp16(smem_u32(&As[buf ^ 1][ar][ac]),     asrc);
            cp16(smem_u32(&As[buf ^ 1][ar][ac + 8]), asrc + 8);
            cp16(smem_u32(&Bs[buf ^ 1][bkr][bc]),     bsrc);
            cp16(smem_u32(&Bs[buf ^ 1][bkr][bc + 8]), bsrc + 8);
            cp_commit();
        }

#pragma unroll
        for (int ks = 0; ks < 2; ks++) {
            uint32_t ra[2][4];
#pragma unroll
            for (int mi = 0; mi < 2; mi++)
                ldsm4(ra[mi], smem_u32(&As[buf][wm + mi * 16 + (l & 15)][ks * 16 + (l >> 4) * 8]));
#pragma unroll
            for (int ntp = 0; ntp < 4; ntp++) {
                uint32_t rb[4];
                ldsm4t(rb, smem_u32(&Bs[buf][ks * 16 + (l & 15)][wn + ntp * 16 + (l >> 4) * 8]));
                mma16816(acc[0][2 * ntp],     ra[0][0], ra[0][1], ra[0][2], ra[0][3], rb[0], rb[1]);
                mma16816(acc[1][2 * ntp],     ra[1][0], ra[1][1], ra[1][2], ra[1][3], rb[0], rb[1]);
                mma16816(acc[0][2 * ntp + 1], ra[0][0], ra[0][1], ra[0][2], ra[0][3], rb[2], rb[3]);
                mma16816(acc[1][2 * ntp + 1], ra[1][0], ra[1][1], ra[1][2], ra[1][3], rb[2], rb[3]);
            }
        }
    }

#pragma unroll
    for (int nt = 0; nt < 8; nt++) {
        int col = bcol + wn + nt * 8 + (l & 3) * 2;
        float2 bv = *(const float2*)&bias[col];
#pragma unroll
        for (int mi = 0; mi < 2; mi++) {
            int r0 = brow + wm + mi * 16 + (l >> 2);
            int r1 = r0 + 8;
            float v0 = acc[mi][nt][0] + bv.x;
            float v1 = acc[mi][nt][1] + bv.y;
            float v2 = acc[mi][nt][2] + bv.x;
            float v3 = acc[mi][nt][3] + bv.y;
            if (OUT_F32) {
                float* C = (float*)Cout;
                *(float2*)&C[(size_t)r0 * N + col] = make_float2(v0, v1);
                *(float2*)&C[(size_t)r1 * N + col] = make_float2(v2, v3);
            } else {
                __half* C = (__half*)Cout;
                *(uint32_t*)&C[(size_t)r0 * N + col] = packf2h(v0, v1);
                *(uint32_t*)&C[(size_t)r1 * N + col] = packf2h(v2, v3);
            }
        }
    }
}

// --------------------- flash attention (fp16 mma, FA2) -----------------------
// 128 queries per block (8 warps x m16), 64-key double-buffered tiles,
// ONE __syncthreads per tile. Paired-chunk schedule: block bx handles chunk bx
// and chunk 31-bx (66 tiles every block). grid = (16, H), 256 threads.
// Softmax in log2 domain; rescale skipped via warp vote.
__global__ __launch_bounds__(256) void flash_mma()
{
    __shared__ __half Ks[2][64][72];   // [key][d]
    __shared__ __half Vs[2][64][72];   // [d][key]

    const int h    = blockIdx.y;
    const int pair = blockIdx.x;       // 0..15
    const int tid  = threadIdx.x;
    const int w    = tid >> 5;
    const int l    = tid & 31;

    const int lr = tid >> 2;           // 0..63  (tile loader row)
    const int lc = (tid & 3) * 16;     // 0/16/32/48 (halves)

#pragma unroll 1
    for (int half = 0; half < 2; half++) {
        const int chunk = half ? (31 - pair) : pair;
        const int qb = chunk * 128;
        const int r0 = qb + w * 16 + (l >> 2);
        const int r1 = r0 + 8;

        // Q fragments pre-scaled by log2(e)/sqrt(64)
        uint32_t qa[4][4];
        {
            const __half2 sc = __float2half2_rn(0.125f * 1.44269504f);
#pragma unroll
            for (int ks = 0; ks < 4; ks++) {
                size_t c0 = (size_t)h * 64 + ks * 16 + (l & 3) * 2;
                __half2 v0 = *(const __half2*)&g_qkvh[(size_t)r0 * QKV_N + c0];
                __half2 v1 = *(const __half2*)&g_qkvh[(size_t)r1 * QKV_N + c0];
                __half2 v2 = *(const __half2*)&g_qkvh[(size_t)r0 * QKV_N + c0 + 8];
                __half2 v3 = *(const __half2*)&g_qkvh[(size_t)r1 * QKV_N + c0 + 8];
                v0 = __hmul2(v0, sc); v1 = __hmul2(v1, sc);
                v2 = __hmul2(v2, sc); v3 = __hmul2(v3, sc);
                qa[ks][0] = *(uint32_t*)&v0; qa[ks][1] = *(uint32_t*)&v1;
                qa[ks][2] = *(uint32_t*)&v2; qa[ks][3] = *(uint32_t*)&v3;
            }
        }

        float o[8][4];
#pragma unroll
        for (int dt = 0; dt < 8; dt++)
#pragma unroll
            for (int j = 0; j < 4; j++) o[dt][j] = 0.0f;
        float m0 = -1e30f, m1 = -1e30f, l0 = 0.0f, l1 = 0.0f;

        // prologue: stage tile 0
        {
            const __half* ksrc = &g_qkvh[(size_t)lr * QKV_N + 768 + h * 64 + lc];
            const __half* vsrc = &g_vt[(size_t)(h * 64 + lr) * T_SEQ + lc];
            cp16(smem_u32(&Ks[0][lr][lc]),     ksrc);
            cp16(smem_u32(&Ks[0][lr][lc + 8]), ksrc + 8);
            cp16(smem_u32(&Vs[0][lr][lc]),     vsrc);
            cp16(smem_u32(&Vs[0][lr][lc + 8]), vsrc + 8);
            cp_commit();
        }

        const int ntiles = qb / 64 + 2;   // keys 0 .. qb+127 (always even)
        for (int it = 0; it < ntiles; it++) {
            const int kt  = it * 64;
            const int buf = it & 1;
            cp_wait0();
            __syncthreads();

            if (it + 1 < ntiles) {
                const int kn = kt + 64;
                const __half* ksrc = &g_qkvh[(size_t)(kn + lr) * QKV_N + 768 + h * 64 + lc];
                const __half* vsrc = &g_vt[(size_t)(h * 64 + lr) * T_SEQ + kn + lc];
                cp16(smem_u32(&Ks[buf ^ 1][lr][lc]),     ksrc);
                cp16(smem_u32(&Ks[buf ^ 1][lr][lc + 8]), ksrc + 8);
                cp16(smem_u32(&Vs[buf ^ 1][lr][lc]),     vsrc);
                cp16(smem_u32(&Vs[buf ^ 1][lr][lc + 8]), vsrc + 8);
                cp_commit();
            }

            // S = Q K^T  (log2-scaled logits)
            float s[8][4];
#pragma unroll
            for (int nt = 0; nt < 8; nt++)
#pragma unroll
                for (int j = 0; j < 4; j++) s[nt][j] = 0.0f;
#pragma unroll
            for (int ks = 0; ks < 4; ks++) {
#pragma unroll
                for (int ntp = 0; ntp < 4; ntp++) {
                    uint32_t rb[4];
                    ldsm4(rb, smem_u32(&Ks[buf][ntp * 16 + (l & 7) + ((l & 16) >> 1)][ks * 16 + (l & 8)]));
                    mma16816(s[2 * ntp],     qa[ks][0], qa[ks][1], qa[ks][2], qa[ks][3], rb[0], rb[1]);
                    mma16816(s[2 * ntp + 1], qa[ks][0], qa[ks][1], qa[ks][2], qa[ks][3], rb[2], rb[3]);
                }
            }

            // causal mask (last two tiles of each chunk only)
            if (kt + 64 > qb) {
#pragma unroll
                for (int nt = 0; nt < 8; nt++) {
                    int col = kt + nt * 8 + (l & 3) * 2;
                    if (col     > r0) s[nt][0] = -1e30f;
                    if (col + 1 > r0) s[nt][1] = -1e30f;
                    if (col     > r1) s[nt][2] = -1e30f;
                    if (col + 1 > r1) s[nt][3] = -1e30f;
                }
            }

            // online softmax (base 2)
            float mt0 = -1e30f, mt1 = -1e30f;
#pragma unroll
            for (int nt = 0; nt < 8; nt++) {
                mt0 = fmaxf(mt0, fmaxf(s[nt][0], s[nt][1]));
                mt1 = fmaxf(mt1, fmaxf(s[nt][2], s[nt][3]));
            }
            mt0 = fmaxf(mt0, __shfl_xor_sync(0xFFFFFFFF, mt0, 1));
            mt0 = fmaxf(mt0, __shfl_xor_sync(0xFFFFFFFF, mt0, 2));
            mt1 = fmaxf(mt1, __shfl_xor_sync(0xFFFFFFFF, mt1, 1));
            mt1 = fmaxf(mt1, __shfl_xor_sync(0xFFFFFFFF, mt1, 2));

            // rescale only when some row max grew (warp vote)
            if (__any_sync(0xFFFFFFFF, (mt0 > m0) | (mt1 > m1))) {
                float m0n = fmaxf(m0, mt0), m1n = fmaxf(m1, mt1);
                float corr0 = ex2(m0 - m0n), corr1 = ex2(m1 - m1n);
                m0 = m0n; m1 = m1n;
                l0 *= corr0; l1 *= corr1;
#pragma unroll
                for (int dt = 0; dt < 8; dt++) {
                    o[dt][0] *= corr0; o[dt][1] *= corr0;
                    o[dt][2] *= corr1; o[dt][3] *= corr1;
                }
            }

            // P = 2^(S - m)
            uint32_t pa[4][4];
#pragma unroll
            for (int nt = 0; nt < 8; nt++) {
                float p0 = ex2(s[nt][0] - m0);
                float p1 = ex2(s[nt][1] - m0);
                float p2 = ex2(s[nt][2] - m1);
                float p3 = ex2(s[nt][3] - m1);
                l0 += p0 + p1;
                l1 += p2 + p3;
                int ks = nt >> 1, hi = (nt & 1) * 2;
                pa[ks][hi + 0] = packf2h(p0, p1);
                pa[ks][hi + 1] = packf2h(p2, p3);
            }

            // O += P V
#pragma unroll
            for (int ks = 0; ks < 4; ks++) {
#pragma unroll
                for (int dtp = 0; dtp < 4; dtp++) {
                    uint32_t rb[4];
                    ldsm4(rb, smem_u32(&Vs[buf][dtp * 16 + (l & 7) + ((l & 16) >> 1)][ks * 16 + (l & 8)]));
                    mma16816(o[2 * dtp],     pa[ks][0], pa[ks][1], pa[ks][2], pa[ks][3], rb[0], rb[1]);
                    mma16816(o[2 * dtp + 1], pa[ks][0], pa[ks][1], pa[ks][2], pa[ks][3], rb[2], rb[3]);
                }
            }
        }

        // finalize
        l0 += __shfl_xor_sync(0xFFFFFFFF, l0, 1);
        l0 += __shfl_xor_sync(0xFFFFFFFF, l0, 2);
        l1 += __shfl_xor_sync(0xFFFFFFFF, l1, 1);
        l1 += __shfl_xor_sync(0xFFFFFFFF, l1, 2);
        float inv0 = 1.0f / l0, inv1 = 1.0f / l1;

#pragma unroll
        for (int dt = 0; dt < 8; dt++) {
            int d = h * 64 + dt * 8 + (l & 3) * 2;
            *(uint32_t*)&g_yh[(size_t)r0 * C_DIM + d] = packf2h(o[dt][0] * inv0, o[dt][1] * inv0);
            *(uint32_t*)&g_yh[(size_t)r1 * C_DIM + d] = packf2h(o[dt][2] * inv1, o[dt][3] * inv1);
        }
    }
}

// ------------------------------------------------------------------------------
extern "C" void kernel_launch(void* const* d_in, const int* in_sizes, int n_in,
                              void* d_out, int out_size)
{
    const float* x      = (const float*)d_in[0];
    const float* w_attn = (const float*)d_in[1];
    const float* b_attn = (const float*)d_in[2];
    const float* w_proj = (const float*)d_in[3];
    const float* b_proj = (const float*)d_in[4];
    float* out = (float*)d_out;

    __half *xh, *wah, *wph, *qkvh, *yh;
    cudaGetSymbolAddress((void**)&xh,   g_xh);
    cudaGetSymbolAddress((void**)&wah,  g_wah);
    cudaGetSymbolAddress((void**)&wph,  g_wph);
    cudaGetSymbolAddress((void**)&qkvh, g_qkvh);
    cudaGetSymbolAddress((void**)&yh,   g_yh);

    {
        int n4 = T_SEQ * C_DIM / 4;
        cvt_f2h<<<(n4 + 255) / 256, 256>>>((const float4*)x, (uint2*)xh, n4);
        n4 = C_DIM * QKV_N / 4;
        cvt_f2h<<<(n4 + 255) / 256, 256>>>((const float4*)w_attn, (uint2*)wah, n4);
        n4 = C_DIM * C_DIM / 4;
        cvt_f2h<<<(n4 + 255) / 256, 256>>>((const float4*)w_proj, (uint2*)wph, n4);
    }

    hgemm_bias<false><<<dim3(QKV_N / 128, T_SEQ / 128), 256>>>(
        xh, wah, b_attn, qkvh, T_SEQ, QKV_N, C_DIM);

    transpose_v<<<dim3(T_SEQ / 32, C_DIM / 32), 256>>>();

    flash_mma<<<dim3(16, H_NUM), 256>>>();

    hgemm_bias<true><<<dim3(C_DIM / 128, T_SEQ / 128), 256>>>(
        yh, wph, b_proj, out, T_SEQ, C_DIM, C_DIM);
}